// round 5
// baseline (speedup 1.0000x reference)
#include <cuda_runtime.h>
#include <cuda_bf16.h>
#include <stdint.h>
#include <string.h>

#define BATCH  4
#define NPTS   64
#define DIM    128
#define NROWS  (NPTS*NPTS)        // 4096
#define KAUG   256                // augmented K: [sd | td]
#define TILE   128
#define NT     (NROWS/TILE)       // 32
#define NPAIR  (NT*(NT+1)/2)      // 528
#define GRID_G (BATCH*NPAIR)      // 2112
#define KCH    64                 // K-chunk (halves) per stage
#define NCHUNK (KAUG/KCH)         // 4
#define LDSH   72                 // padded smem row (halves): 144B, conflict-free
#define MATB   (TILE*LDSH*2)      // 18432 B per matrix per buffer
#define BUFB   (2*MATB)           // 36864 B per buffer (A+B)
#define SMTOT  (2*BUFB)           // 73728 B dynamic smem

__device__ __nv_bfloat16 g_X[(size_t)BATCH*NROWS*KAUG];  // [sd | td]
__device__ __nv_bfloat16 g_Y[(size_t)BATCH*NROWS*KAUG];  // [sd | -td]
__device__ double g_acc;
__device__ unsigned int g_done;

__device__ __forceinline__ uint32_t pack_bf2(float a, float b) {
    __nv_bfloat162 v = __floats2bfloat162_rn(a, b);
    uint32_t u; memcpy(&u, &v, 4); return u;
}

// ---------------------------------------------------------------- diff kernel
__global__ __launch_bounds__(256) void diff_k(const float* __restrict__ student,
                                              const float* __restrict__ teacher) {
    if (blockIdx.x == 0 && threadIdx.x == 0) { g_acc = 0.0; g_done = 0u; }
    int w = (blockIdx.x * blockDim.x + threadIdx.x) >> 5;
    int lane = threadIdx.x & 31;
    int b = w >> 12;
    int ij = w & 4095;
    int i = ij >> 6, j = ij & 63;

    const float4* si = (const float4*)(student + (size_t)(b*NPTS + i)*DIM);
    const float4* sj = (const float4*)(student + (size_t)(b*NPTS + j)*DIM);
    const float4* ti = (const float4*)(teacher + (size_t)(b*NPTS + i)*DIM);
    const float4* tj = (const float4*)(teacher + (size_t)(b*NPTS + j)*DIM);
    float4 a = si[lane], c = sj[lane], e = ti[lane], f = tj[lane];
    float s0 = a.x-c.x, s1 = a.y-c.y, s2 = a.z-c.z, s3 = a.w-c.w;
    float t0 = e.x-f.x, t1 = e.y-f.y, t2 = e.z-f.z, t3 = e.w-f.w;
    float ss = s0*s0+s1*s1+s2*s2+s3*s3;
    float st = t0*t0+t1*t1+t2*t2+t3*t3;
    #pragma unroll
    for (int o = 16; o; o >>= 1) {
        ss += __shfl_xor_sync(0xffffffffu, ss, o);
        st += __shfl_xor_sync(0xffffffffu, st, o);
    }
    float ks = 1.0f / fmaxf(sqrtf(ss), 1e-12f);
    float kt = 1.0f / fmaxf(sqrtf(st), 1e-12f);
    s0*=ks; s1*=ks; s2*=ks; s3*=ks;
    t0*=kt; t1*=kt; t2*=kt; t3*=kt;

    size_t r = (size_t)w * KAUG;
    uint2 sv, tv, tn;
    sv.x = pack_bf2(s0, s1);  sv.y = pack_bf2(s2, s3);
    tv.x = pack_bf2(t0, t1);  tv.y = pack_bf2(t2, t3);
    tn.x = pack_bf2(-t0, -t1); tn.y = pack_bf2(-t2, -t3);
    *(uint2*)(&g_X[r + lane*4])       = sv;
    *(uint2*)(&g_X[r + 128 + lane*4]) = tv;
    *(uint2*)(&g_Y[r + lane*4])       = sv;
    *(uint2*)(&g_Y[r + 128 + lane*4]) = tn;
}

// ---------------------------------------------------------------- mma helpers
__device__ __forceinline__ void ldsm_x4(uint32_t* r, const void* p) {
    uint32_t addr = (uint32_t)__cvta_generic_to_shared(p);
    asm volatile("ldmatrix.sync.aligned.m8n8.x4.shared.b16 {%0,%1,%2,%3}, [%4];"
                 : "=r"(r[0]), "=r"(r[1]), "=r"(r[2]), "=r"(r[3]) : "r"(addr));
}
__device__ __forceinline__ void mma_bf16(float* c, const uint32_t* a, const uint32_t* b) {
    asm volatile(
        "mma.sync.aligned.m16n8k16.row.col.f32.bf16.bf16.f32 "
        "{%0,%1,%2,%3},{%4,%5,%6,%7},{%8,%9},{%0,%1,%2,%3};\n"
        : "+f"(c[0]), "+f"(c[1]), "+f"(c[2]), "+f"(c[3])
        : "r"(a[0]), "r"(a[1]), "r"(a[2]), "r"(a[3]), "r"(b[0]), "r"(b[1]));
}
__device__ __forceinline__ void cp16(void* dst, const void* src) {
    uint32_t d = (uint32_t)__cvta_generic_to_shared(dst);
    asm volatile("cp.async.cg.shared.global [%0], [%1], 16;" :: "r"(d), "l"(src));
}
#define CP_COMMIT() asm volatile("cp.async.commit_group;" ::: "memory")
#define CP_WAIT1()  asm volatile("cp.async.wait_group 1;" ::: "memory")
#define CP_WAIT0()  asm volatile("cp.async.wait_group 0;" ::: "memory")

// ---------------------------------------------------------------- gram kernel
// One CTA = (batch, upper-tri 128x128 tile pair). D = X_I · Y_J^T, K=256 in
// 4 chunks of 64, cp.async double-buffered, 4 unrolled K-steps per barrier
// interval. Smooth-L1 epilogue on regs, last CTA writes the final mean.
__global__ __launch_bounds__(256, 2) void gram_k(float* __restrict__ out) {
    extern __shared__ __align__(16) char smem[];
    __shared__ float wsum[8];

    int tid = threadIdx.x, wid = tid >> 5, lane = tid & 31;
    int bid = blockIdx.x;
    int b = bid / NPAIR;
    int p = bid - b * NPAIR;
    int ti_ = 0, rem = p;
    while (rem >= NT - ti_) { rem -= NT - ti_; ti_++; }
    int tj_ = ti_ + rem;

    const __nv_bfloat16* gI = g_X + ((size_t)b * NROWS + (size_t)ti_ * TILE) * KAUG;
    const __nv_bfloat16* gJ = g_Y + ((size_t)b * NROWS + (size_t)tj_ * TILE) * KAUG;

    int wm = wid & 3;   // 4 warps along M (32 rows each)
    int wn = wid >> 2;  // 2 warps along N (64 cols each)

    float acc[2][8][4];
    #pragma unroll
    for (int f = 0; f < 2; f++)
        #pragma unroll
        for (int n = 0; n < 8; n++)
            #pragma unroll
            for (int e = 0; e < 4; e++) acc[f][n][e] = 0.f;

    int a_r = (lane & 7) + ((lane >> 3) & 1) * 8;
    int a_k = (lane >> 4) * 8;
    int b_r = (lane & 7) + ((lane >> 4) & 1) * 8;
    int b_k = ((lane >> 3) & 1) * 8;

    // chunk loader: per matrix 128 rows x 64 halves (128B = 8 int4 per row)
    auto load_chunk = [&](int c) {
        char* buf = smem + (c & 1) * BUFB;
        #pragma unroll
        for (int u = 0; u < 4; u++) {
            int idx = tid + u * 256;           // 0..1023
            int row = idx >> 3, seg = idx & 7;
            size_t goff = (size_t)row * KAUG + c * KCH + seg * 8;
            char* d = buf + row * (LDSH * 2) + seg * 16;
            cp16(d, gI + goff);
            cp16(d + MATB, gJ + goff);
        }
        CP_COMMIT();
    };

    load_chunk(0);

    #pragma unroll
    for (int c = 0; c < NCHUNK; c++) {
        if (c + 1 < NCHUNK) { load_chunk(c + 1); CP_WAIT1(); }
        else CP_WAIT0();
        __syncthreads();

        const __nv_bfloat16* shA = (const __nv_bfloat16*)(smem + (c & 1) * BUFB);
        const __nv_bfloat16* shB = (const __nv_bfloat16*)(smem + (c & 1) * BUFB + MATB);
        #pragma unroll
        for (int ks = 0; ks < KCH / 16; ks++) {
            uint32_t afr[2][4];
            uint32_t bfr[8][2];
            #pragma unroll
            for (int f = 0; f < 2; f++) {
                int row = wm * 32 + f * 16 + a_r;
                ldsm_x4(afr[f], &shA[row * LDSH + ks * 16 + a_k]);
            }
            #pragma unroll
            for (int g = 0; g < 4; g++) {
                int row = wn * 64 + g * 16 + b_r;
                uint32_t t4[4];
                ldsm_x4(t4, &shB[row * LDSH + ks * 16 + b_k]);
                bfr[2*g][0] = t4[0]; bfr[2*g][1] = t4[1];
                bfr[2*g+1][0] = t4[2]; bfr[2*g+1][1] = t4[3];
            }
            #pragma unroll
            for (int f = 0; f < 2; f++)
                #pragma unroll
                for (int n = 0; n < 8; n++)
                    mma_bf16(acc[f][n], afr[f], bfr[n]);
        }
        __syncthreads();
    }

    // smooth-L1 epilogue + block reduction
    float lsum = 0.f;
    #pragma unroll
    for (int f = 0; f < 2; f++)
        #pragma unroll
        for (int n = 0; n < 8; n++)
            #pragma unroll
            for (int e = 0; e < 4; e++) {
                float d = acc[f][n][e];
                float ad = fabsf(d);
                lsum += (ad < 1.0f) ? 0.5f * d * d : ad - 0.5f;
            }
    #pragma unroll
    for (int o = 16; o; o >>= 1) lsum += __shfl_xor_sync(0xffffffffu, lsum, o);
    if (lane == 0) wsum[wid] = lsum;
    __syncthreads();
    if (tid == 0) {
        float t = 0.f;
        #pragma unroll
        for (int w = 0; w < 8; w++) t += wsum[w];
        if (ti_ != tj_) t *= 2.0f;
        atomicAdd(&g_acc, (double)t);
        __threadfence();
        unsigned int ticket = atomicAdd(&g_done, 1u);
        if (ticket == GRID_G - 1) {
            double v = *((volatile double*)&g_acc);
            out[0] = (float)(v / ((double)BATCH * NROWS * NROWS));
        }
    }
}

extern "C" void kernel_launch(void* const* d_in, const int* in_sizes, int n_in,
                              void* d_out, int out_size) {
    const float* student = (const float*)d_in[0];
    const float* teacher = (const float*)d_in[1];
    cudaFuncSetAttribute(gram_k, cudaFuncAttributeMaxDynamicSharedMemorySize, SMTOT);
    diff_k<<<(BATCH * NROWS) / 8, 256>>>(student, teacher);
    gram_k<<<GRID_G, 256, SMTOT>>>((float*)d_out);
}

// round 6
// speedup vs baseline: 1.4200x; 1.4200x over previous
#include <cuda_runtime.h>
#include <cuda_bf16.h>
#include <stdint.h>
#include <string.h>

#define BATCH  4
#define NPTS   64
#define DIM    128
#define NROWS  (NPTS*NPTS)        // 4096
#define KAUG   256                // augmented K: [sd | td]
#define TILE   128
#define NT     (NROWS/TILE)       // 32
#define NPAIR  (NT*(NT+1)/2)      // 528
#define GRID_G (BATCH*NPAIR)      // 2112
#define KCH    32                 // K-chunk (halves) per stage
#define NCHUNK (KAUG/KCH)         // 8
#define NSTAGE 3                  // circular buffer stages
#define LDSH   40                 // padded smem row (halves): 80B, conflict-free
#define MATB   (TILE*LDSH*2)      // 10240 B per matrix per stage
#define BUFB   (2*MATB)           // 20480 B per stage (A+B)
#define SMTOT  (NSTAGE*BUFB)      // 61440 B dynamic smem

__device__ __nv_bfloat16 g_X[(size_t)BATCH*NROWS*KAUG];  // [sd | td]
__device__ __nv_bfloat16 g_Y[(size_t)BATCH*NROWS*KAUG];  // [sd | -td]
__device__ double g_acc;
__device__ unsigned int g_done;

__device__ __forceinline__ uint32_t pack_bf2(float a, float b) {
    __nv_bfloat162 v = __floats2bfloat162_rn(a, b);
    uint32_t u; memcpy(&u, &v, 4); return u;
}

// ---------------------------------------------------------------- diff kernel
__global__ __launch_bounds__(256) void diff_k(const float* __restrict__ student,
                                              const float* __restrict__ teacher) {
    if (blockIdx.x == 0 && threadIdx.x == 0) { g_acc = 0.0; g_done = 0u; }
    int w = (blockIdx.x * blockDim.x + threadIdx.x) >> 5;
    int lane = threadIdx.x & 31;
    int b = w >> 12;
    int ij = w & 4095;
    int i = ij >> 6, j = ij & 63;

    const float4* si = (const float4*)(student + (size_t)(b*NPTS + i)*DIM);
    const float4* sj = (const float4*)(student + (size_t)(b*NPTS + j)*DIM);
    const float4* ti = (const float4*)(teacher + (size_t)(b*NPTS + i)*DIM);
    const float4* tj = (const float4*)(teacher + (size_t)(b*NPTS + j)*DIM);
    float4 a = si[lane], c = sj[lane], e = ti[lane], f = tj[lane];
    float s0 = a.x-c.x, s1 = a.y-c.y, s2 = a.z-c.z, s3 = a.w-c.w;
    float t0 = e.x-f.x, t1 = e.y-f.y, t2 = e.z-f.z, t3 = e.w-f.w;
    float ss = s0*s0+s1*s1+s2*s2+s3*s3;
    float st = t0*t0+t1*t1+t2*t2+t3*t3;
    #pragma unroll
    for (int o = 16; o; o >>= 1) {
        ss += __shfl_xor_sync(0xffffffffu, ss, o);
        st += __shfl_xor_sync(0xffffffffu, st, o);
    }
    float ks = 1.0f / fmaxf(sqrtf(ss), 1e-12f);
    float kt = 1.0f / fmaxf(sqrtf(st), 1e-12f);
    s0*=ks; s1*=ks; s2*=ks; s3*=ks;
    t0*=kt; t1*=kt; t2*=kt; t3*=kt;

    size_t r = (size_t)w * KAUG;
    uint2 sv, tv, tn;
    sv.x = pack_bf2(s0, s1);  sv.y = pack_bf2(s2, s3);
    tv.x = pack_bf2(t0, t1);  tv.y = pack_bf2(t2, t3);
    tn.x = pack_bf2(-t0, -t1); tn.y = pack_bf2(-t2, -t3);
    *(uint2*)(&g_X[r + lane*4])       = sv;
    *(uint2*)(&g_X[r + 128 + lane*4]) = tv;
    *(uint2*)(&g_Y[r + lane*4])       = sv;
    *(uint2*)(&g_Y[r + 128 + lane*4]) = tn;
}

// ---------------------------------------------------------------- mma helpers
__device__ __forceinline__ void ldsm_x4(uint32_t* r, const void* p) {
    uint32_t addr = (uint32_t)__cvta_generic_to_shared(p);
    asm volatile("ldmatrix.sync.aligned.m8n8.x4.shared.b16 {%0,%1,%2,%3}, [%4];"
                 : "=r"(r[0]), "=r"(r[1]), "=r"(r[2]), "=r"(r[3]) : "r"(addr));
}
__device__ __forceinline__ void mma_bf16(float* c, const uint32_t* a, const uint32_t* b) {
    asm volatile(
        "mma.sync.aligned.m16n8k16.row.col.f32.bf16.bf16.f32 "
        "{%0,%1,%2,%3},{%4,%5,%6,%7},{%8,%9},{%0,%1,%2,%3};\n"
        : "+f"(c[0]), "+f"(c[1]), "+f"(c[2]), "+f"(c[3])
        : "r"(a[0]), "r"(a[1]), "r"(a[2]), "r"(a[3]), "r"(b[0]), "r"(b[1]));
}
__device__ __forceinline__ void cp16(void* dst, const void* src) {
    uint32_t d = (uint32_t)__cvta_generic_to_shared(dst);
    asm volatile("cp.async.cg.shared.global [%0], [%1], 16;" :: "r"(d), "l"(src));
}
#define CP_COMMIT() asm volatile("cp.async.commit_group;" ::: "memory")
#define CP_WAIT1()  asm volatile("cp.async.wait_group 1;" ::: "memory")
#define CP_WAIT0()  asm volatile("cp.async.wait_group 0;" ::: "memory")

// ---------------------------------------------------------------- gram kernel
// One CTA = (batch, upper-tri 128x128 tile pair). D = X_I · Y_J^T, K=256 in
// 8 chunks of 32, cp.async 3-stage circular buffer, ONE __syncthreads per
// chunk:  wait(c) -> sync -> load(c+2) -> mma(c).
// Smooth-L1 epilogue on regs, last CTA writes the final mean.
__global__ __launch_bounds__(256, 2) void gram_k(float* __restrict__ out) {
    extern __shared__ __align__(16) char smem[];
    __shared__ float wsum[8];

    int tid = threadIdx.x, wid = tid >> 5, lane = tid & 31;
    int bid = blockIdx.x;
    int b = bid / NPAIR;
    int p = bid - b * NPAIR;
    int ti_ = 0, rem = p;
    while (rem >= NT - ti_) { rem -= NT - ti_; ti_++; }
    int tj_ = ti_ + rem;

    const __nv_bfloat16* gI = g_X + ((size_t)b * NROWS + (size_t)ti_ * TILE) * KAUG;
    const __nv_bfloat16* gJ = g_Y + ((size_t)b * NROWS + (size_t)tj_ * TILE) * KAUG;

    int wm = wid & 3;   // 4 warps along M (32 rows each)
    int wn = wid >> 2;  // 2 warps along N (64 cols each)

    float acc[2][8][4];
    #pragma unroll
    for (int f = 0; f < 2; f++)
        #pragma unroll
        for (int n = 0; n < 8; n++)
            #pragma unroll
            for (int e = 0; e < 4; e++) acc[f][n][e] = 0.f;

    int a_r = (lane & 7) + ((lane >> 3) & 1) * 8;
    int a_k = (lane >> 4) * 8;
    int b_r = (lane & 7) + ((lane >> 4) & 1) * 8;
    int b_k = ((lane >> 3) & 1) * 8;

    // chunk loader: per matrix 128 rows x 32 halves (64B = 4 int4 per row)
    auto load_chunk = [&](int c) {
        char* buf = smem + (c % NSTAGE) * BUFB;
        #pragma unroll
        for (int u = 0; u < 2; u++) {
            int idx = tid + u * 256;           // 0..511
            int row = idx >> 2, seg = idx & 3;
            size_t goff = (size_t)row * KAUG + c * KCH + seg * 8;
            char* d = buf + row * (LDSH * 2) + seg * 16;
            cp16(d, gI + goff);
            cp16(d + MATB, gJ + goff);
        }
        CP_COMMIT();
    };

    load_chunk(0);
    load_chunk(1);

    #pragma unroll
    for (int c = 0; c < NCHUNK; c++) {
        if (c < NCHUNK - 1) CP_WAIT1();     // chunk c delivered
        else                CP_WAIT0();
        __syncthreads();                     // everyone done reading stage c%3
        if (c + 2 < NCHUNK) load_chunk(c + 2);   // writes stage (c+2)%3

        const __nv_bfloat16* shA = (const __nv_bfloat16*)(smem + (c % NSTAGE) * BUFB);
        const __nv_bfloat16* shB = (const __nv_bfloat16*)(smem + (c % NSTAGE) * BUFB + MATB);
        #pragma unroll
        for (int ks = 0; ks < KCH / 16; ks++) {
            uint32_t afr[2][4];
            uint32_t bfr[8][2];
            #pragma unroll
            for (int f = 0; f < 2; f++) {
                int row = wm * 32 + f * 16 + a_r;
                ldsm_x4(afr[f], &shA[row * LDSH + ks * 16 + a_k]);
            }
            #pragma unroll
            for (int g = 0; g < 4; g++) {
                int row = wn * 64 + g * 16 + b_r;
                uint32_t t4[4];
                ldsm_x4(t4, &shB[row * LDSH + ks * 16 + b_k]);
                bfr[2*g][0] = t4[0]; bfr[2*g][1] = t4[1];
                bfr[2*g+1][0] = t4[2]; bfr[2*g+1][1] = t4[3];
            }
            #pragma unroll
            for (int f = 0; f < 2; f++)
                #pragma unroll
                for (int n = 0; n < 8; n++)
                    mma_bf16(acc[f][n], afr[f], bfr[n]);
        }
    }

    // smooth-L1 epilogue + block reduction
    float lsum = 0.f;
    #pragma unroll
    for (int f = 0; f < 2; f++)
        #pragma unroll
        for (int n = 0; n < 8; n++)
            #pragma unroll
            for (int e = 0; e < 4; e++) {
                float d = acc[f][n][e];
                float ad = fabsf(d);
                lsum += (ad < 1.0f) ? 0.5f * d * d : ad - 0.5f;
            }
    #pragma unroll
    for (int o = 16; o; o >>= 1) lsum += __shfl_xor_sync(0xffffffffu, lsum, o);
    if (lane == 0) wsum[wid] = lsum;
    __syncthreads();
    if (tid == 0) {
        float t = 0.f;
        #pragma unroll
        for (int w = 0; w < 8; w++) t += wsum[w];
        if (ti_ != tj_) t *= 2.0f;
        atomicAdd(&g_acc, (double)t);
        __threadfence();
        unsigned int ticket = atomicAdd(&g_done, 1u);
        if (ticket == GRID_G - 1) {
            double v = *((volatile double*)&g_acc);
            out[0] = (float)(v / ((double)BATCH * NROWS * NROWS));
        }
    }
}

extern "C" void kernel_launch(void* const* d_in, const int* in_sizes, int n_in,
                              void* d_out, int out_size) {
    const float* student = (const float*)d_in[0];
    const float* teacher = (const float*)d_in[1];
    cudaFuncSetAttribute(gram_k, cudaFuncAttributeMaxDynamicSharedMemorySize, SMTOT);
    diff_k<<<(BATCH * NROWS) / 8, 256>>>(student, teacher);
    gram_k<<<GRID_G, 256, SMTOT>>>((float*)d_out);
}

// round 7
// speedup vs baseline: 3.3491x; 2.3585x over previous
#include <cuda_runtime.h>
#include <cuda_bf16.h>
#include <stdint.h>
#include <string.h>

#define BATCH  4
#define NPTS   64
#define DIM    128
#define NFULL  (NPTS*NPTS)        // 4096 (reference row count)
#define NPRED  2016               // rows with i<j
#define NROWSC 2048               // padded compacted rows
#define KAUG   256                // augmented K: [sd | td]
#define TILE   128
#define NBT    (NROWSC/TILE)      // 16
#define NPAIRB (NBT*(NBT+1)/2)    // 136
#define GRID_G (BATCH*NPAIRB)     // 544
#define KCH    32                 // K-chunk (halves) per stage
#define NCHUNK (KAUG/KCH)         // 8
#define NSTAGE 3                  // circular buffer stages
#define LDSH   40                 // padded smem row (halves): 80B, conflict-free
#define MATB   (TILE*LDSH*2)      // 10240 B per matrix per stage
#define BUFB   (2*MATB)           // 20480 B per stage (A+B)
#define SMTOT  (NSTAGE*BUFB)      // 61440 B dynamic smem

__device__ __nv_bfloat16 g_X[(size_t)BATCH*NROWSC*KAUG];  // [sd | td]
__device__ __nv_bfloat16 g_Y[(size_t)BATCH*NROWSC*KAUG];  // [sd | -td]
__device__ double g_acc;
__device__ unsigned int g_done;

__device__ __forceinline__ uint32_t pack_bf2(float a, float b) {
    __nv_bfloat162 v = __floats2bfloat162_rn(a, b);
    uint32_t u; memcpy(&u, &v, 4); return u;
}

// ---------------------------------------------------------------- diff kernel
// One warp per compacted row r in [0, 2048): rows < 2016 hold pair (i<j),
// rows >= 2016 are zero padding. 8192 warps total.
__global__ __launch_bounds__(256) void diff_k(const float* __restrict__ student,
                                              const float* __restrict__ teacher) {
    if (blockIdx.x == 0 && threadIdx.x == 0) { g_acc = 0.0; g_done = 0u; }
    int w = (blockIdx.x * blockDim.x + threadIdx.x) >> 5;
    int lane = threadIdx.x & 31;
    int b = w >> 11;              // batch
    int r = w & 2047;             // compacted row
    size_t ro = ((size_t)b * NROWSC + r) * KAUG;

    if (r >= NPRED) {             // zero padding rows
        uint2 z = make_uint2(0u, 0u);
        *(uint2*)(&g_X[ro + lane*4])       = z;
        *(uint2*)(&g_X[ro + 128 + lane*4]) = z;
        *(uint2*)(&g_Y[ro + lane*4])       = z;
        *(uint2*)(&g_Y[ro + 128 + lane*4]) = z;
        return;
    }

    // decode r -> (i, j) with i < j  (row-major over i, 63-i entries per i)
    int i = 0, rem = r, cnt = NPTS - 1;
    while (rem >= cnt) { rem -= cnt; cnt--; i++; }
    int j = i + 1 + rem;

    const float4* si = (const float4*)(student + (size_t)(b*NPTS + i)*DIM);
    const float4* sj = (const float4*)(student + (size_t)(b*NPTS + j)*DIM);
    const float4* ti = (const float4*)(teacher + (size_t)(b*NPTS + i)*DIM);
    const float4* tj = (const float4*)(teacher + (size_t)(b*NPTS + j)*DIM);
    float4 a = si[lane], c = sj[lane], e = ti[lane], f = tj[lane];
    float s0 = a.x-c.x, s1 = a.y-c.y, s2 = a.z-c.z, s3 = a.w-c.w;
    float t0 = e.x-f.x, t1 = e.y-f.y, t2 = e.z-f.z, t3 = e.w-f.w;
    float ss = s0*s0+s1*s1+s2*s2+s3*s3;
    float st = t0*t0+t1*t1+t2*t2+t3*t3;
    #pragma unroll
    for (int o = 16; o; o >>= 1) {
        ss += __shfl_xor_sync(0xffffffffu, ss, o);
        st += __shfl_xor_sync(0xffffffffu, st, o);
    }
    float ks = 1.0f / fmaxf(sqrtf(ss), 1e-12f);
    float kt = 1.0f / fmaxf(sqrtf(st), 1e-12f);
    s0*=ks; s1*=ks; s2*=ks; s3*=ks;
    t0*=kt; t1*=kt; t2*=kt; t3*=kt;

    uint2 sv, tv, tn;
    sv.x = pack_bf2(s0, s1);  sv.y = pack_bf2(s2, s3);
    tv.x = pack_bf2(t0, t1);  tv.y = pack_bf2(t2, t3);
    tn.x = pack_bf2(-t0, -t1); tn.y = pack_bf2(-t2, -t3);
    *(uint2*)(&g_X[ro + lane*4])       = sv;
    *(uint2*)(&g_X[ro + 128 + lane*4]) = tv;
    *(uint2*)(&g_Y[ro + lane*4])       = sv;
    *(uint2*)(&g_Y[ro + 128 + lane*4]) = tn;
}

// ---------------------------------------------------------------- mma helpers
__device__ __forceinline__ void ldsm_x4(uint32_t* r, const void* p) {
    uint32_t addr = (uint32_t)__cvta_generic_to_shared(p);
    asm volatile("ldmatrix.sync.aligned.m8n8.x4.shared.b16 {%0,%1,%2,%3}, [%4];"
                 : "=r"(r[0]), "=r"(r[1]), "=r"(r[2]), "=r"(r[3]) : "r"(addr));
}
__device__ __forceinline__ void mma_bf16(float* c, const uint32_t* a, const uint32_t* b) {
    asm volatile(
        "mma.sync.aligned.m16n8k16.row.col.f32.bf16.bf16.f32 "
        "{%0,%1,%2,%3},{%4,%5,%6,%7},{%8,%9},{%0,%1,%2,%3};\n"
        : "+f"(c[0]), "+f"(c[1]), "+f"(c[2]), "+f"(c[3])
        : "r"(a[0]), "r"(a[1]), "r"(a[2]), "r"(a[3]), "r"(b[0]), "r"(b[1]));
}
__device__ __forceinline__ void cp16(void* dst, const void* src) {
    uint32_t d = (uint32_t)__cvta_generic_to_shared(dst);
    asm volatile("cp.async.cg.shared.global [%0], [%1], 16;" :: "r"(d), "l"(src));
}
#define CP_COMMIT() asm volatile("cp.async.commit_group;" ::: "memory")
#define CP_WAIT1()  asm volatile("cp.async.wait_group 1;" ::: "memory")
#define CP_WAIT0()  asm volatile("cp.async.wait_group 0;" ::: "memory")

// ---------------------------------------------------------------- gram kernel
// One CTA = (batch, upper-tri 128x128 tile pair of the COMPACTED 2048-row set).
// D = X_I · Y_J^T, K=256 in 8 chunks of 32, 3-stage cp.async ring, one
// __syncthreads per chunk. Smooth-L1 epilogue; class multiplicity x4 applied
// at the end; last CTA writes the mean over the FULL (4096^2) element count.
__global__ __launch_bounds__(256, 2) void gram_k(float* __restrict__ out) {
    extern __shared__ __align__(16) char smem[];
    __shared__ float wsum[8];

    int tid = threadIdx.x, wid = tid >> 5, lane = tid & 31;
    int bid = blockIdx.x;
    int b = bid / NPAIRB;
    int p = bid - b * NPAIRB;
    int ti_ = 0, rem = p;
    while (rem >= NBT - ti_) { rem -= NBT - ti_; ti_++; }
    int tj_ = ti_ + rem;

    const __nv_bfloat16* gI = g_X + ((size_t)b * NROWSC + (size_t)ti_ * TILE) * KAUG;
    const __nv_bfloat16* gJ = g_Y + ((size_t)b * NROWSC + (size_t)tj_ * TILE) * KAUG;

    int wm = wid & 3;   // 4 warps along M (32 rows each)
    int wn = wid >> 2;  // 2 warps along N (64 cols each)

    float acc[2][8][4];
    #pragma unroll
    for (int f = 0; f < 2; f++)
        #pragma unroll
        for (int n = 0; n < 8; n++)
            #pragma unroll
            for (int e = 0; e < 4; e++) acc[f][n][e] = 0.f;

    int a_r = (lane & 7) + ((lane >> 3) & 1) * 8;
    int a_k = (lane >> 4) * 8;
    int b_r = (lane & 7) + ((lane >> 4) & 1) * 8;
    int b_k = ((lane >> 3) & 1) * 8;

    auto load_chunk = [&](int c) {
        char* buf = smem + (c % NSTAGE) * BUFB;
        #pragma unroll
        for (int u = 0; u < 2; u++) {
            int idx = tid + u * 256;           // 0..511
            int row = idx >> 2, seg = idx & 3;
            size_t goff = (size_t)row * KAUG + c * KCH + seg * 8;
            char* d = buf + row * (LDSH * 2) + seg * 16;
            cp16(d, gI + goff);
            cp16(d + MATB, gJ + goff);
        }
        CP_COMMIT();
    };

    load_chunk(0);
    load_chunk(1);

    #pragma unroll
    for (int c = 0; c < NCHUNK; c++) {
        if (c < NCHUNK - 1) CP_WAIT1();
        else                CP_WAIT0();
        __syncthreads();
        if (c + 2 < NCHUNK) load_chunk(c + 2);

        const __nv_bfloat16* shA = (const __nv_bfloat16*)(smem + (c % NSTAGE) * BUFB);
        const __nv_bfloat16* shB = (const __nv_bfloat16*)(smem + (c % NSTAGE) * BUFB + MATB);
        #pragma unroll
        for (int ks = 0; ks < KCH / 16; ks++) {
            uint32_t afr[2][4];
            uint32_t bfr[8][2];
            #pragma unroll
            for (int f = 0; f < 2; f++) {
                int row = wm * 32 + f * 16 + a_r;
                ldsm_x4(afr[f], &shA[row * LDSH + ks * 16 + a_k]);
            }
            #pragma unroll
            for (int g = 0; g < 4; g++) {
                int row = wn * 64 + g * 16 + b_r;
                uint32_t t4[4];
                ldsm_x4(t4, &shB[row * LDSH + ks * 16 + b_k]);
                bfr[2*g][0] = t4[0]; bfr[2*g][1] = t4[1];
                bfr[2*g+1][0] = t4[2]; bfr[2*g+1][1] = t4[3];
            }
            #pragma unroll
            for (int f = 0; f < 2; f++)
                #pragma unroll
                for (int n = 0; n < 8; n++)
                    mma_bf16(acc[f][n], afr[f], bfr[n]);
        }
    }

    // smooth-L1 epilogue + block reduction
    float lsum = 0.f;
    #pragma unroll
    for (int f = 0; f < 2; f++)
        #pragma unroll
        for (int n = 0; n < 8; n++)
            #pragma unroll
            for (int e = 0; e < 4; e++) {
                float d = acc[f][n][e];
                float ad = fabsf(d);
                lsum += (ad < 1.0f) ? 0.5f * d * d : ad - 0.5f;
            }
    #pragma unroll
    for (int o = 16; o; o >>= 1) lsum += __shfl_xor_sync(0xffffffffu, lsum, o);
    if (lane == 0) wsum[wid] = lsum;
    __syncthreads();
    if (tid == 0) {
        float t = 0.f;
        #pragma unroll
        for (int w = 0; w < 8; w++) t += wsum[w];
        if (ti_ != tj_) t *= 2.0f;   // transpose symmetry within compacted set
        atomicAdd(&g_acc, (double)t);
        __threadfence();
        unsigned int ticket = atomicAdd(&g_done, 1u);
        if (ticket == GRID_G - 1) {
            double v = *((volatile double*)&g_acc);
            // x4 sign-class multiplicity; mean over full 4096^2 per batch
            out[0] = (float)(4.0 * v / ((double)BATCH * NFULL * NFULL));
        }
    }
}

extern "C" void kernel_launch(void* const* d_in, const int* in_sizes, int n_in,
                              void* d_out, int out_size) {
    const float* student = (const float*)d_in[0];
    const float* teacher = (const float*)d_in[1];
    cudaFuncSetAttribute(gram_k, cudaFuncAttributeMaxDynamicSharedMemorySize, SMTOT);
    diff_k<<<(BATCH * NROWSC) / 8, 256>>>(student, teacher);
    gram_k<<<GRID_G, 256, SMTOT>>>((float*)d_out);
}